// round 6
// baseline (speedup 1.0000x reference)
#include <cuda_runtime.h>
#include <math.h>

#define NMAX 50000
#define EMAX 800000
#define GMAX 100
#define FDIM 256
#define AMAXS 128   // edges kept in smem (global fallback beyond)
#define CAP   16    // src rows cached in smem during pass A

// ---------------- scratch (device globals) ---------------------------------
__device__ float g_h[NMAX * FDIM];
__device__ float g_xl[NMAX * FDIM];
__device__ float g_xr[NMAX * FDIM];
__device__ float g_alpha[EMAX * 4];
__device__ float g_pool[GMAX * FDIM];
__device__ float g_cnt[GMAX];
__device__ int   g_deg[NMAX];
__device__ int   g_cur[NMAX];
__device__ int   g_rowptr[NMAX + 1];
__device__ int2  g_epair[EMAX];          // (src, ea bits) packed

// ---------------- f32x2 helpers ---------------------------------------------
typedef unsigned long long ull;
__device__ __forceinline__ ull fma2(ull a, ull b, ull c) {
    ull d;
    asm("fma.rn.f32x2 %0, %1, %2, %3;" : "=l"(d) : "l"(a), "l"(b), "l"(c));
    return d;
}
__device__ __forceinline__ ull pack2(float lo, float hi) {
    ull o;
    asm("mov.b64 %0, {%1, %2};" : "=l"(o)
        : "r"(__float_as_uint(lo)), "r"(__float_as_uint(hi)));
    return o;
}
__device__ __forceinline__ void unpack2(ull v, float& lo, float& hi) {
    unsigned a, b;
    asm("mov.b64 {%0, %1}, %2;" : "=r"(a), "=r"(b) : "l"(v));
    lo = __uint_as_float(a); hi = __uint_as_float(b);
}

// ---------------- launch 0: encoder + hist + zeroing --------------------------
__global__ void enc_hist_kernel(const float* __restrict__ x,
                                const float* __restrict__ W,
                                const float* __restrict__ b,
                                const int* __restrict__ dst,
                                const int* __restrict__ batch,
                                int N, int E, int G) {
    int idx = blockIdx.x * blockDim.x + threadIdx.x;
    if (idx < N) { g_cur[idx] = 0; atomicAdd(&g_cnt[batch[idx]], 1.f); }
    if (idx < G * FDIM) g_pool[idx] = 0.f;
    if (idx < E) atomicAdd(&g_deg[dst[idx]], 1);
    if (idx < N * 64) {
        int n = idx >> 6, j = idx & 63;
        const float* xrow = x + n * 8;
        float acc = b[j];
#pragma unroll
        for (int k = 0; k < 8; ++k) acc = fmaf(xrow[k], W[k * 64 + j], acc);
        g_h[n * 64 + j] = fmaxf(acc, 0.f);
    }
}
// NOTE: g_deg and g_cnt must start at zero. They are zeroed at the END of the
// pipeline (see mlp_kernel epilogue + gat epilogue) so replays stay correct.

// ---------------- launch 1: single-block scan ---------------------------------
__global__ __launch_bounds__(1024) void csr_scan(int N) {
    __shared__ int s[1024];
    const int tid = threadIdx.x;
    const int PER = (N + 1023) / 1024;
    const int base = tid * PER;
    int run = 0;
    for (int k = 0; k < PER; ++k) {
        int i = base + k;
        if (i < N) run += g_deg[i];
    }
    s[tid] = run;
    __syncthreads();
    for (int off = 1; off < 1024; off <<= 1) {
        int t = (tid >= off) ? s[tid - off] : 0;
        __syncthreads();
        s[tid] += t;
        __syncthreads();
    }
    int pre = s[tid] - run;
    if (tid == 0) g_rowptr[0] = 0;
    run = pre;
    for (int k = 0; k < PER; ++k) {
        int i = base + k;
        if (i < N) { run += g_deg[i]; g_rowptr[i + 1] = run; g_deg[i] = 0; }
    }
}

// ---------------- gemm body (device fn, used by fused kernel + gemm2) --------
template <int K>
__device__ __forceinline__ void gemm_body(
    int blk, const float* __restrict__ Wl, const float* __restrict__ bl,
    const float* __restrict__ Wr, const float* __restrict__ br, int N,
    float* hs /* K*34 floats smem */) {
    constexpr int MB = 32, LD = 34;
    const int n0 = blk * MB;
    const int j = threadIdx.x;

    for (int idx = threadIdx.x; idx < MB * K; idx += 256) {
        int m = idx / K, k = idx - m * K;
        int n = n0 + m;
        hs[k * LD + m] = (n < N) ? g_h[(size_t)n * K + k] : 0.f;
    }
    __syncthreads();

    ull accl[16], accr[16];
    float blj = bl[j], brj = br[j];
#pragma unroll
    for (int p = 0; p < 16; ++p) { accl[p] = pack2(blj, blj); accr[p] = pack2(brj, brj); }

#pragma unroll 4
    for (int k = 0; k < K; ++k) {
        float wl = Wl[k * 256 + j];
        float wr = Wr[k * 256 + j];
        ull wl2 = pack2(wl, wl), wr2 = pack2(wr, wr);
        const float* hrow = &hs[k * LD];
#pragma unroll
        for (int p = 0; p < 16; ++p) {
            ull hp = *reinterpret_cast<const ull*>(hrow + 2 * p);
            accl[p] = fma2(hp, wl2, accl[p]);
            accr[p] = fma2(hp, wr2, accr[p]);
        }
    }
#pragma unroll
    for (int p = 0; p < 16; ++p) {
        float l0, l1, r0, r1;
        unpack2(accl[p], l0, l1);
        unpack2(accr[p], r0, r1);
        int n = n0 + 2 * p;
        if (n < N)     { g_xl[(size_t)n * 256 + j] = l0; g_xr[(size_t)n * 256 + j] = r0; }
        if (n + 1 < N) { g_xl[(size_t)(n + 1) * 256 + j] = l1; g_xr[(size_t)(n + 1) * 256 + j] = r1; }
    }
}

// ---------------- launch 2: scatter + gemm1 (role-split blocks) --------------
__global__ __launch_bounds__(256) void scatter_gemm1(
    const int* __restrict__ src, const int* __restrict__ dst,
    const float* __restrict__ ea,
    const float* __restrict__ Wl, const float* __restrict__ bl,
    const float* __restrict__ Wr, const float* __restrict__ br,
    int N, int E, int ngemm) {
    __shared__ __align__(16) float hs[64 * 34];
    if ((int)blockIdx.x < ngemm) {
        gemm_body<64>(blockIdx.x, Wl, bl, Wr, br, N, hs);
    } else {
        int e = (blockIdx.x - ngemm) * 256 + threadIdx.x;
        if (e < E) {
            int d = dst[e];
            int pos = g_rowptr[d] + atomicAdd(&g_cur[d], 1);
            g_epair[pos] = make_int2(src[e], __float_as_int(ea[e]));
        }
    }
}

// ---------------- launch 4: gemm2 ---------------------------------------------
__global__ __launch_bounds__(256) void gemm2_kernel(
    const float* __restrict__ Wl, const float* __restrict__ bl,
    const float* __restrict__ Wr, const float* __restrict__ br, int N) {
    __shared__ __align__(16) float hs[256 * 34];
    gemm_body<256>(blockIdx.x, Wl, bl, Wr, br, N, hs);
}

// ---------------- launches 3 & 5: fused GATv2 edge phase ----------------------
template <bool LAST>
__global__ __launch_bounds__(256) void gat_fused(
    const float* __restrict__ We, const float* __restrict__ att,
    const float* __restrict__ bias, const int* __restrict__ batch) {
    __shared__ __align__(16) float4 xr4[64], We4[64], att4[64];
    __shared__ float denom_s[4];
    __shared__ int2  ep_s[AMAXS];
    __shared__ float alpha_s[AMAXS * 4];
    __shared__ __align__(16) float4 xlc4[CAP * 64];

    const int d = blockIdx.x;
    const int tid = threadIdx.x;
    const int start = g_rowptr[d];
    const int deg = g_rowptr[d + 1] - start;
    const bool inm = (deg <= AMAXS);

    // prefetch edge list (coalesced) — overlaps with xr/We/att loads
    if (inm && tid < deg) ep_s[tid] = g_epair[start + tid];

    if (tid < 64)        xr4[tid]       = reinterpret_cast<const float4*>(g_xr + (size_t)d * 256)[tid];
    else if (tid < 128)  We4[tid - 64]  = reinterpret_cast<const float4*>(We)[tid - 64];
    else if (tid < 192)  att4[tid - 128]= reinterpret_cast<const float4*>(att)[tid - 128];
    __syncthreads();

    if (deg > 0) {
        float* abuf = inm ? alpha_s : &g_alpha[(size_t)start * 4];

        // ---- pass A: warp per edge; two float4 gathers; cache rows < CAP ----
        const int warp = tid >> 5, lane = tid & 31;
        for (int i = warp; i < deg; i += 8) {
            int2 ep = inm ? ep_s[i] : g_epair[start + i];
            int s = ep.x;
            float w = __int_as_float(ep.y);
            const float4* xl4 = reinterpret_cast<const float4*>(g_xl + (size_t)s * 256);
            float4 a0 = xl4[lane];
            float4 a1 = xl4[lane + 32];
            if (i < CAP) { xlc4[i * 64 + lane] = a0; xlc4[i * 64 + lane + 32] = a1; }

            float4 x0 = xr4[lane],      e0 = We4[lane],      t0 = att4[lane];
            float4 x1 = xr4[lane + 32], e1 = We4[lane + 32], t1 = att4[lane + 32];

            float v, p0, p1;
            v = a0.x + x0.x + w * e0.x; v = (v > 0.f) ? v : 0.2f * v; p0 = v * t0.x;
            v = a0.y + x0.y + w * e0.y; v = (v > 0.f) ? v : 0.2f * v; p0 = fmaf(v, t0.y, p0);
            v = a0.z + x0.z + w * e0.z; v = (v > 0.f) ? v : 0.2f * v; p0 = fmaf(v, t0.z, p0);
            v = a0.w + x0.w + w * e0.w; v = (v > 0.f) ? v : 0.2f * v; p0 = fmaf(v, t0.w, p0);
            v = a1.x + x1.x + w * e1.x; v = (v > 0.f) ? v : 0.2f * v; p1 = v * t1.x;
            v = a1.y + x1.y + w * e1.y; v = (v > 0.f) ? v : 0.2f * v; p1 = fmaf(v, t1.y, p1);
            v = a1.z + x1.z + w * e1.z; v = (v > 0.f) ? v : 0.2f * v; p1 = fmaf(v, t1.z, p1);
            v = a1.w + x1.w + w * e1.w; v = (v > 0.f) ? v : 0.2f * v; p1 = fmaf(v, t1.w, p1);

#pragma unroll
            for (int off = 8; off; off >>= 1) {
                p0 += __shfl_xor_sync(0xffffffffu, p0, off);
                p1 += __shfl_xor_sync(0xffffffffu, p1, off);
            }
            if ((lane & 15) == 0) {
                int hh = lane >> 4;
                abuf[i * 4 + hh]     = p0;
                abuf[i * 4 + 2 + hh] = p1;
            }
        }
        __syncthreads();

        // ---- softmax: warp h handles head h ----
        if (warp < 4) {
            const int h = warp;
            float m = -__int_as_float(0x7f800000);
            for (int i = lane; i < deg; i += 32) m = fmaxf(m, abuf[i * 4 + h]);
#pragma unroll
            for (int off = 16; off; off >>= 1)
                m = fmaxf(m, __shfl_xor_sync(0xffffffffu, m, off));
            float sm = 0.f;
            for (int i = lane; i < deg; i += 32) {
                float ex = __expf(abuf[i * 4 + h] - m);
                abuf[i * 4 + h] = ex;
                sm += ex;
            }
#pragma unroll
            for (int off = 16; off; off >>= 1)
                sm += __shfl_xor_sync(0xffffffffu, sm, off);
            if (lane == 0) denom_s[h] = sm + 1e-16f;
        }
        __syncthreads();

        // ---- pass B: aggregate (thread = feature), smem cache + spill ----
        const int h = tid >> 6;
        const float* xlc = reinterpret_cast<const float*>(xlc4);
        float acc = 0.f;
        int dc = (deg < CAP) ? deg : CAP;
#pragma unroll 4
        for (int i = 0; i < dc; ++i)
            acc = fmaf(abuf[i * 4 + h], xlc[i * 256 + tid], acc);
        for (int i = CAP; i < deg; ++i) {
            int s = inm ? ep_s[i].x : g_epair[start + i].x;
            acc = fmaf(abuf[i * 4 + h], g_xl[(size_t)s * 256 + tid], acc);
        }
        acc /= denom_s[h];

        float val = fmaxf(acc + bias[tid], 0.f);
        if (LAST) atomicAdd(&g_pool[batch[d] * 256 + tid], val);
        else      g_h[(size_t)d * 256 + tid] = val;
    } else {
        float val = fmaxf(bias[tid], 0.f);
        if (LAST) atomicAdd(&g_pool[batch[d] * 256 + tid], val);
        else      g_h[(size_t)d * 256 + tid] = val;
    }
    // epilogue of last gat: reset cnt scratch for next replay
    if (LAST && tid < GMAX && d == 0) ; // (g_cnt reset handled in mlp)
}

// ---------------- launch 6: head MLP + scratch reset ---------------------------
__global__ __launch_bounds__(128) void mlp_kernel(
    const float* __restrict__ p1W, const float* __restrict__ p1b,
    const float* __restrict__ lng, const float* __restrict__ lnb,
    const float* __restrict__ p2W, const float* __restrict__ p2b,
    float* __restrict__ out, int G) {
    int g = blockIdx.x;
    __shared__ float ps[256];
    __shared__ float zs[128];
    __shared__ float red[128];
    float cnt = fmaxf(g_cnt[g], 1.f);
    for (int k = threadIdx.x; k < 256; k += 128)
        ps[k] = g_pool[g * 256 + k] / cnt;
    __syncthreads();
    // reset per-graph scratch for next graph replay
    if (threadIdx.x == 0) g_cnt[g] = 0.f;

    int j = threadIdx.x;
    float z = p1b[j];
    for (int k = 0; k < 256; ++k) z = fmaf(ps[k], p1W[k * 128 + j], z);

    red[j] = z;
    __syncthreads();
    for (int s = 64; s; s >>= 1) { if (j < s) red[j] += red[j + s]; __syncthreads(); }
    float mu = red[0] * (1.f / 128.f);
    __syncthreads();
    float dz = z - mu;
    red[j] = dz * dz;
    __syncthreads();
    for (int s = 64; s; s >>= 1) { if (j < s) red[j] += red[j + s]; __syncthreads(); }
    float var = red[0] * (1.f / 128.f);
    float zn = dz * rsqrtf(var + 1e-5f) * lng[j] + lnb[j];
    zs[j] = fmaxf(zn, 0.f);
    __syncthreads();

    if (j < 64) {
        float o = p2b[j];
        for (int k = 0; k < 128; ++k) o = fmaf(zs[k], p2W[k * 64 + j], o);
        out[g * 64 + j] = fmaxf(o, 0.f);
    }
}

// ---------------- driver ----------------------------------------------------------
extern "C" void kernel_launch(void* const* d_in, const int* in_sizes, int n_in,
                              void* d_out, int out_size) {
    const float* x      = (const float*)d_in[0];
    const int*   ei     = (const int*)  d_in[1];
    const float* ea     = (const float*)d_in[2];
    const int*   batch  = (const int*)  d_in[3];
    const float* enc_W  = (const float*)d_in[4];
    const float* enc_b  = (const float*)d_in[5];
    const float* g1_Wl  = (const float*)d_in[6];
    const float* g1_bl  = (const float*)d_in[7];
    const float* g1_Wr  = (const float*)d_in[8];
    const float* g1_br  = (const float*)d_in[9];
    const float* g1_We  = (const float*)d_in[10];
    const float* g1_att = (const float*)d_in[11];
    const float* g1_bias= (const float*)d_in[12];
    const float* g2_Wl  = (const float*)d_in[13];
    const float* g2_bl  = (const float*)d_in[14];
    const float* g2_Wr  = (const float*)d_in[15];
    const float* g2_br  = (const float*)d_in[16];
    const float* g2_We  = (const float*)d_in[17];
    const float* g2_att = (const float*)d_in[18];
    const float* g2_bias= (const float*)d_in[19];
    const float* p1_W   = (const float*)d_in[20];
    const float* p1_b   = (const float*)d_in[21];
    const float* ln_g   = (const float*)d_in[22];
    const float* ln_b   = (const float*)d_in[23];
    const float* p2_W   = (const float*)d_in[24];
    const float* p2_b   = (const float*)d_in[25];

    const int N = in_sizes[3];
    const int E = in_sizes[2];
    const int G = out_size / 64;
    const int* src = ei;
    const int* dst = ei + E;
    const int T = 256;

    // 0: encoder + degree hist + graph counts + pool zero
    // (g_deg zeroed by csr_scan epilogue, g_cnt by mlp epilogue, g_cur by scan? -> g_cur zeroed here)
    enc_hist_kernel<<<(N * 64 + T - 1) / T, T>>>(x, enc_W, enc_b, dst, batch, N, E, G);
    // 1: rowptr scan (also re-zeros g_deg for next replay)
    csr_scan<<<1, 1024>>>(N);
    // 2: edge scatter + layer-1 projections (role-split grid)
    {
        int ngemm = (N + 31) / 32;
        int nscat = (E + T - 1) / T;
        scatter_gemm1<<<ngemm + nscat, T>>>(src, dst, ea, g1_Wl, g1_bl,
                                            g1_Wr, g1_br, N, E, ngemm);
    }
    // 3: layer-1 fused GAT  (profiled launch)
    gat_fused<false><<<N, 256>>>(g1_We, g1_att, g1_bias, batch);
    // 4: layer-2 projections
    gemm2_kernel<<<(N + 31) / 32, 256>>>(g2_Wl, g2_bl, g2_Wr, g2_br, N);
    // 5: layer-2 fused GAT -> pool
    gat_fused<true><<<N, 256>>>(g2_We, g2_att, g2_bias, batch);
    // 6: head MLP (+ g_cnt reset)
    mlp_kernel<<<G, 128>>>(p1_W, p1_b, ln_g, ln_b, p2_W, p2_b, (float*)d_out, G);
}

// round 7
// speedup vs baseline: 1.0613x; 1.0613x over previous
#include <cuda_runtime.h>
#include <math.h>

#define NMAX 50000
#define EMAX 800000
#define GMAX 100
#define FDIM 256
#define AMAXS 128   // edges prefetched to smem (global fallback beyond)

// ---------------- scratch (device globals) ---------------------------------
__device__ float g_h[NMAX * FDIM];
__device__ float g_xl[NMAX * FDIM];
__device__ float g_xr[NMAX * FDIM];
__device__ float g_pool[GMAX * FDIM];
__device__ float g_cnt[GMAX];
__device__ int   g_deg[NMAX];
__device__ int   g_cur[NMAX];
__device__ int   g_rowptr[NMAX + 1];
__device__ int2  g_epair[EMAX];          // (src, ea bits) packed

// ---------------- f32x2 helpers ---------------------------------------------
typedef unsigned long long ull;
__device__ __forceinline__ ull fma2(ull a, ull b, ull c) {
    ull d;
    asm("fma.rn.f32x2 %0, %1, %2, %3;" : "=l"(d) : "l"(a), "l"(b), "l"(c));
    return d;
}
__device__ __forceinline__ ull pack2(float lo, float hi) {
    ull o;
    asm("mov.b64 %0, {%1, %2};" : "=l"(o)
        : "r"(__float_as_uint(lo)), "r"(__float_as_uint(hi)));
    return o;
}
__device__ __forceinline__ void unpack2(ull v, float& lo, float& hi) {
    unsigned a, b;
    asm("mov.b64 {%0, %1}, %2;" : "=r"(a), "=r"(b) : "l"(v));
    lo = __uint_as_float(a); hi = __uint_as_float(b);
}

// ---------------- launch 0: encoder + hist + zeroing --------------------------
__global__ void enc_hist_kernel(const float* __restrict__ x,
                                const float* __restrict__ W,
                                const float* __restrict__ b,
                                const int* __restrict__ dst,
                                const int* __restrict__ batch,
                                int N, int E, int G) {
    int idx = blockIdx.x * blockDim.x + threadIdx.x;
    if (idx < N) { g_cur[idx] = 0; atomicAdd(&g_cnt[batch[idx]], 1.f); }
    if (idx < G * FDIM) g_pool[idx] = 0.f;
    if (idx < E) atomicAdd(&g_deg[dst[idx]], 1);
    if (idx < N * 64) {
        int n = idx >> 6, j = idx & 63;
        const float* xrow = x + n * 8;
        float acc = b[j];
#pragma unroll
        for (int k = 0; k < 8; ++k) acc = fmaf(xrow[k], W[k * 64 + j], acc);
        g_h[n * 64 + j] = fmaxf(acc, 0.f);
    }
}

// ---------------- launch 1: single-block scan (re-zeros g_deg) ----------------
__global__ __launch_bounds__(1024) void csr_scan(int N) {
    __shared__ int s[1024];
    const int tid = threadIdx.x;
    const int PER = (N + 1023) / 1024;
    const int base = tid * PER;
    int run = 0;
    for (int k = 0; k < PER; ++k) {
        int i = base + k;
        if (i < N) run += g_deg[i];
    }
    s[tid] = run;
    __syncthreads();
    for (int off = 1; off < 1024; off <<= 1) {
        int t = (tid >= off) ? s[tid - off] : 0;
        __syncthreads();
        s[tid] += t;
        __syncthreads();
    }
    int pre = s[tid] - run;
    if (tid == 0) g_rowptr[0] = 0;
    run = pre;
    for (int k = 0; k < PER; ++k) {
        int i = base + k;
        if (i < N) { run += g_deg[i]; g_rowptr[i + 1] = run; g_deg[i] = 0; }
    }
}

// ---------------- gemm body (device fn) ---------------------------------------
template <int K>
__device__ __forceinline__ void gemm_body(
    int blk, const float* __restrict__ Wl, const float* __restrict__ bl,
    const float* __restrict__ Wr, const float* __restrict__ br, int N,
    float* hs) {
    constexpr int MB = 32, LD = 34;
    const int n0 = blk * MB;
    const int j = threadIdx.x;

    for (int idx = threadIdx.x; idx < MB * K; idx += 256) {
        int m = idx / K, k = idx - m * K;
        int n = n0 + m;
        hs[k * LD + m] = (n < N) ? g_h[(size_t)n * K + k] : 0.f;
    }
    __syncthreads();

    ull accl[16], accr[16];
    float blj = bl[j], brj = br[j];
#pragma unroll
    for (int p = 0; p < 16; ++p) { accl[p] = pack2(blj, blj); accr[p] = pack2(brj, brj); }

#pragma unroll 4
    for (int k = 0; k < K; ++k) {
        float wl = Wl[k * 256 + j];
        float wr = Wr[k * 256 + j];
        ull wl2 = pack2(wl, wl), wr2 = pack2(wr, wr);
        const float* hrow = &hs[k * LD];
#pragma unroll
        for (int p = 0; p < 16; ++p) {
            ull hp = *reinterpret_cast<const ull*>(hrow + 2 * p);
            accl[p] = fma2(hp, wl2, accl[p]);
            accr[p] = fma2(hp, wr2, accr[p]);
        }
    }
#pragma unroll
    for (int p = 0; p < 16; ++p) {
        float l0, l1, r0, r1;
        unpack2(accl[p], l0, l1);
        unpack2(accr[p], r0, r1);
        int n = n0 + 2 * p;
        if (n < N)     { g_xl[(size_t)n * 256 + j] = l0; g_xr[(size_t)n * 256 + j] = r0; }
        if (n + 1 < N) { g_xl[(size_t)(n + 1) * 256 + j] = l1; g_xr[(size_t)(n + 1) * 256 + j] = r1; }
    }
}

// ---------------- launch 2: scatter + gemm1 (role-split blocks) --------------
__global__ __launch_bounds__(256) void scatter_gemm1(
    const int* __restrict__ src, const int* __restrict__ dst,
    const float* __restrict__ ea,
    const float* __restrict__ Wl, const float* __restrict__ bl,
    const float* __restrict__ Wr, const float* __restrict__ br,
    int N, int E, int ngemm) {
    __shared__ __align__(16) float hs[64 * 34];
    if ((int)blockIdx.x < ngemm) {
        gemm_body<64>(blockIdx.x, Wl, bl, Wr, br, N, hs);
    } else {
        int e = (blockIdx.x - ngemm) * 256 + threadIdx.x;
        if (e < E) {
            int d = dst[e];
            int pos = g_rowptr[d] + atomicAdd(&g_cur[d], 1);
            g_epair[pos] = make_int2(src[e], __float_as_int(ea[e]));
        }
    }
}

// ---------------- launch 4: gemm2 ---------------------------------------------
__global__ __launch_bounds__(256) void gemm2_kernel(
    const float* __restrict__ Wl, const float* __restrict__ bl,
    const float* __restrict__ Wr, const float* __restrict__ br, int N) {
    __shared__ __align__(16) float hs[256 * 34];
    gemm_body<256>(blockIdx.x, Wl, bl, Wr, br, N, hs);
}

// ---------------- launches 3 & 5: single-pass online-softmax GAT --------------
// Warp streams its edges once; per-lane register accumulators (8 feats) with
// per-head online (max,sum). One merge sync. No alpha buffer, no row cache.
template <bool LAST>
__global__ __launch_bounds__(256) void gat_fused(
    const float* __restrict__ We, const float* __restrict__ att,
    const float* __restrict__ bias, const int* __restrict__ batch) {
    __shared__ __align__(16) float4 xr4[64], We4[64], att4[64];
    __shared__ int2  ep_s[AMAXS];
    __shared__ __align__(16) float macc[8 * 256];  // per-warp partial sums
    __shared__ float mm[8][4], ms[8][4];           // per-warp per-head (max,sum)

    const int d = blockIdx.x;
    const int tid = threadIdx.x;
    const int start = g_rowptr[d];
    const int deg = g_rowptr[d + 1] - start;
    const bool inm = (deg <= AMAXS);

    if (inm && tid < deg) ep_s[tid] = g_epair[start + tid];
    if (tid < 64)        xr4[tid]        = reinterpret_cast<const float4*>(g_xr + (size_t)d * 256)[tid];
    else if (tid < 128)  We4[tid - 64]   = reinterpret_cast<const float4*>(We)[tid - 64];
    else if (tid < 192)  att4[tid - 128] = reinterpret_cast<const float4*>(att)[tid - 128];
    __syncthreads();

    const int warp = tid >> 5, lane = tid & 31;

    if (deg > 0) {
        // loop-invariant operands in registers
        const float4 x0 = xr4[lane],      e0 = We4[lane],      t0 = att4[lane];
        const float4 x1 = xr4[lane + 32], e1 = We4[lane + 32], t1 = att4[lane + 32];

        float4 acc0 = {0.f, 0.f, 0.f, 0.f}, acc1 = {0.f, 0.f, 0.f, 0.f};
        const float NEG_INF = -__int_as_float(0x7f800000);
        float m0 = NEG_INF, m1 = NEG_INF, s0 = 0.f, s1 = 0.f;

        for (int i = warp; i < deg; i += 8) {
            int2 ep = inm ? ep_s[i] : g_epair[start + i];
            const float4* xl4 = reinterpret_cast<const float4*>(g_xl + (size_t)ep.x * 256);
            float w = __int_as_float(ep.y);
            float4 a0 = xl4[lane];
            float4 a1 = xl4[lane + 32];

            float v, p0, p1;
            v = a0.x + x0.x + w * e0.x; v = (v > 0.f) ? v : 0.2f * v; p0 = v * t0.x;
            v = a0.y + x0.y + w * e0.y; v = (v > 0.f) ? v : 0.2f * v; p0 = fmaf(v, t0.y, p0);
            v = a0.z + x0.z + w * e0.z; v = (v > 0.f) ? v : 0.2f * v; p0 = fmaf(v, t0.z, p0);
            v = a0.w + x0.w + w * e0.w; v = (v > 0.f) ? v : 0.2f * v; p0 = fmaf(v, t0.w, p0);
            v = a1.x + x1.x + w * e1.x; v = (v > 0.f) ? v : 0.2f * v; p1 = v * t1.x;
            v = a1.y + x1.y + w * e1.y; v = (v > 0.f) ? v : 0.2f * v; p1 = fmaf(v, t1.y, p1);
            v = a1.z + x1.z + w * e1.z; v = (v > 0.f) ? v : 0.2f * v; p1 = fmaf(v, t1.z, p1);
            v = a1.w + x1.w + w * e1.w; v = (v > 0.f) ? v : 0.2f * v; p1 = fmaf(v, t1.w, p1);

            // reduce within 16-lane halves; afterwards every lane of a half
            // holds its own head's alpha (p0: heads 0/1, p1: heads 2/3)
#pragma unroll
            for (int off = 8; off; off >>= 1) {
                p0 += __shfl_xor_sync(0xffffffffu, p0, off);
                p1 += __shfl_xor_sync(0xffffffffu, p1, off);
            }

            // online softmax update for this lane's two heads
            float nm0 = fmaxf(m0, p0);
            float sc0 = __expf(m0 - nm0);
            float ew0 = __expf(p0 - nm0);
            s0 = fmaf(s0, sc0, ew0); m0 = nm0;
            float nm1 = fmaxf(m1, p1);
            float sc1 = __expf(m1 - nm1);
            float ew1 = __expf(p1 - nm1);
            s1 = fmaf(s1, sc1, ew1); m1 = nm1;

            acc0.x = fmaf(acc0.x, sc0, ew0 * a0.x);
            acc0.y = fmaf(acc0.y, sc0, ew0 * a0.y);
            acc0.z = fmaf(acc0.z, sc0, ew0 * a0.z);
            acc0.w = fmaf(acc0.w, sc0, ew0 * a0.w);
            acc1.x = fmaf(acc1.x, sc1, ew1 * a1.x);
            acc1.y = fmaf(acc1.y, sc1, ew1 * a1.y);
            acc1.z = fmaf(acc1.z, sc1, ew1 * a1.z);
            acc1.w = fmaf(acc1.w, sc1, ew1 * a1.w);
        }

        // publish warp partials
        float4* mp = reinterpret_cast<float4*>(macc);
        mp[warp * 64 + lane]      = acc0;
        mp[warp * 64 + lane + 32] = acc1;
        if ((lane & 15) == 0) {
            int hh = lane >> 4;           // 0 or 1
            mm[warp][hh]     = m0; ms[warp][hh]     = s0;   // heads 0/1
            mm[warp][2 + hh] = m1; ms[warp][2 + hh] = s1;   // heads 2/3
        }
        __syncthreads();

        // merge: thread = feature j
        const int h = tid >> 6;
        float M = NEG_INF;
#pragma unroll
        for (int w2 = 0; w2 < 8; ++w2) M = fmaxf(M, mm[w2][h]);
        float accj = 0.f, den = 0.f;
#pragma unroll
        for (int w2 = 0; w2 < 8; ++w2) {
            float f = __expf(mm[w2][h] - M);
            accj = fmaf(macc[w2 * 256 + tid], f, accj);
            den  = fmaf(ms[w2][h], f, den);
        }
        accj /= (den + 1e-16f);

        float val = fmaxf(accj + bias[tid], 0.f);
        if (LAST) atomicAdd(&g_pool[batch[d] * 256 + tid], val);
        else      g_h[(size_t)d * 256 + tid] = val;
    } else {
        float val = fmaxf(bias[tid], 0.f);
        if (LAST) atomicAdd(&g_pool[batch[d] * 256 + tid], val);
        else      g_h[(size_t)d * 256 + tid] = val;
    }
}

// ---------------- launch 6: head MLP + scratch reset ---------------------------
__global__ __launch_bounds__(128) void mlp_kernel(
    const float* __restrict__ p1W, const float* __restrict__ p1b,
    const float* __restrict__ lng, const float* __restrict__ lnb,
    const float* __restrict__ p2W, const float* __restrict__ p2b,
    float* __restrict__ out, int G) {
    int g = blockIdx.x;
    __shared__ float ps[256];
    __shared__ float zs[128];
    __shared__ float red[128];
    float cnt = fmaxf(g_cnt[g], 1.f);
    for (int k = threadIdx.x; k < 256; k += 128)
        ps[k] = g_pool[g * 256 + k] / cnt;
    __syncthreads();
    if (threadIdx.x == 0) g_cnt[g] = 0.f;   // reset for next replay

    int j = threadIdx.x;
    float z = p1b[j];
    for (int k = 0; k < 256; ++k) z = fmaf(ps[k], p1W[k * 128 + j], z);

    red[j] = z;
    __syncthreads();
    for (int s = 64; s; s >>= 1) { if (j < s) red[j] += red[j + s]; __syncthreads(); }
    float mu = red[0] * (1.f / 128.f);
    __syncthreads();
    float dz = z - mu;
    red[j] = dz * dz;
    __syncthreads();
    for (int s = 64; s; s >>= 1) { if (j < s) red[j] += red[j + s]; __syncthreads(); }
    float var = red[0] * (1.f / 128.f);
    float zn = dz * rsqrtf(var + 1e-5f) * lng[j] + lnb[j];
    zs[j] = fmaxf(zn, 0.f);
    __syncthreads();

    if (j < 64) {
        float o = p2b[j];
        for (int k = 0; k < 128; ++k) o = fmaf(zs[k], p2W[k * 64 + j], o);
        out[g * 64 + j] = fmaxf(o, 0.f);
    }
}

// ---------------- driver ----------------------------------------------------------
extern "C" void kernel_launch(void* const* d_in, const int* in_sizes, int n_in,
                              void* d_out, int out_size) {
    const float* x      = (const float*)d_in[0];
    const int*   ei     = (const int*)  d_in[1];
    const float* ea     = (const float*)d_in[2];
    const int*   batch  = (const int*)  d_in[3];
    const float* enc_W  = (const float*)d_in[4];
    const float* enc_b  = (const float*)d_in[5];
    const float* g1_Wl  = (const float*)d_in[6];
    const float* g1_bl  = (const float*)d_in[7];
    const float* g1_Wr  = (const float*)d_in[8];
    const float* g1_br  = (const float*)d_in[9];
    const float* g1_We  = (const float*)d_in[10];
    const float* g1_att = (const float*)d_in[11];
    const float* g1_bias= (const float*)d_in[12];
    const float* g2_Wl  = (const float*)d_in[13];
    const float* g2_bl  = (const float*)d_in[14];
    const float* g2_Wr  = (const float*)d_in[15];
    const float* g2_br  = (const float*)d_in[16];
    const float* g2_We  = (const float*)d_in[17];
    const float* g2_att = (const float*)d_in[18];
    const float* g2_bias= (const float*)d_in[19];
    const float* p1_W   = (const float*)d_in[20];
    const float* p1_b   = (const float*)d_in[21];
    const float* ln_g   = (const float*)d_in[22];
    const float* ln_b   = (const float*)d_in[23];
    const float* p2_W   = (const float*)d_in[24];
    const float* p2_b   = (const float*)d_in[25];

    const int N = in_sizes[3];
    const int E = in_sizes[2];
    const int G = out_size / 64;
    const int* src = ei;
    const int* dst = ei + E;
    const int T = 256;

    // 0: encoder + degree hist + graph counts + pool zero
    enc_hist_kernel<<<(N * 64 + T - 1) / T, T>>>(x, enc_W, enc_b, dst, batch, N, E, G);
    // 1: rowptr scan (re-zeros g_deg)
    csr_scan<<<1, 1024>>>(N);
    // 2: edge scatter + layer-1 projections (role-split grid)
    {
        int ngemm = (N + 31) / 32;
        int nscat = (E + T - 1) / T;
        scatter_gemm1<<<ngemm + nscat, T>>>(src, dst, ea, g1_Wl, g1_bl,
                                            g1_Wr, g1_br, N, E, ngemm);
    }
    // 3: layer-1 fused GAT (profiled launch)
    gat_fused<false><<<N, 256>>>(g1_We, g1_att, g1_bias, batch);
    // 4: layer-2 projections
    gemm2_kernel<<<(N + 31) / 32, 256>>>(g2_Wl, g2_bl, g2_Wr, g2_br, N);
    // 5: layer-2 fused GAT -> pool
    gat_fused<true><<<N, 256>>>(g2_We, g2_att, g2_bias, batch);
    // 6: head MLP (+ g_cnt reset)
    mlp_kernel<<<G, 128>>>(p1_W, p1_b, ln_g, ln_b, p2_W, p2_b, (float*)d_out, G);
}

// round 8
// speedup vs baseline: 1.2595x; 1.1868x over previous
#include <cuda_runtime.h>
#include <math.h>

#define NMAX 50000
#define EMAX 800000
#define GMAX 100
#define FDIM 256

// ---------------- scratch (device globals) ---------------------------------
__device__ float g_h[NMAX * FDIM];
__device__ float g_xl[NMAX * FDIM];
__device__ float g_xr[NMAX * FDIM];
__device__ float g_pool[GMAX * FDIM];
__device__ float g_cnt[GMAX];
__device__ int   g_deg[NMAX];
__device__ int   g_cur[NMAX];
__device__ int   g_rowptr[NMAX + 1];
__device__ int2  g_epair[EMAX];          // (src, ea bits) packed

// ---------------- f32x2 helpers ---------------------------------------------
typedef unsigned long long ull;
__device__ __forceinline__ ull fma2(ull a, ull b, ull c) {
    ull d;
    asm("fma.rn.f32x2 %0, %1, %2, %3;" : "=l"(d) : "l"(a), "l"(b), "l"(c));
    return d;
}
__device__ __forceinline__ ull pack2(float lo, float hi) {
    ull o;
    asm("mov.b64 %0, {%1, %2};" : "=l"(o)
        : "r"(__float_as_uint(lo)), "r"(__float_as_uint(hi)));
    return o;
}
__device__ __forceinline__ void unpack2(ull v, float& lo, float& hi) {
    unsigned a, b;
    asm("mov.b64 {%0, %1}, %2;" : "=r"(a), "=r"(b) : "l"(v));
    lo = __uint_as_float(a); hi = __uint_as_float(b);
}

// ---------------- launch 0: encoder + hist + zeroing --------------------------
__global__ void enc_hist_kernel(const float* __restrict__ x,
                                const float* __restrict__ W,
                                const float* __restrict__ b,
                                const int* __restrict__ dst,
                                const int* __restrict__ batch,
                                int N, int E, int G) {
    int idx = blockIdx.x * blockDim.x + threadIdx.x;
    if (idx < N) { g_cur[idx] = 0; atomicAdd(&g_cnt[batch[idx]], 1.f); }
    if (idx < G * FDIM) g_pool[idx] = 0.f;
    if (idx < E) atomicAdd(&g_deg[dst[idx]], 1);
    if (idx < N * 64) {
        int n = idx >> 6, j = idx & 63;
        const float* xrow = x + n * 8;
        float acc = b[j];
#pragma unroll
        for (int k = 0; k < 8; ++k) acc = fmaf(xrow[k], W[k * 64 + j], acc);
        g_h[n * 64 + j] = fmaxf(acc, 0.f);
    }
}

// ---------------- launch 1: single-block scan (re-zeros g_deg) ----------------
__global__ __launch_bounds__(1024) void csr_scan(int N) {
    __shared__ int s[1024];
    const int tid = threadIdx.x;
    const int PER = (N + 1023) / 1024;
    const int base = tid * PER;
    int run = 0;
    for (int k = 0; k < PER; ++k) {
        int i = base + k;
        if (i < N) run += g_deg[i];
    }
    s[tid] = run;
    __syncthreads();
    for (int off = 1; off < 1024; off <<= 1) {
        int t = (tid >= off) ? s[tid - off] : 0;
        __syncthreads();
        s[tid] += t;
        __syncthreads();
    }
    int pre = s[tid] - run;
    if (tid == 0) g_rowptr[0] = 0;
    run = pre;
    for (int k = 0; k < PER; ++k) {
        int i = base + k;
        if (i < N) { run += g_deg[i]; g_rowptr[i + 1] = run; g_deg[i] = 0; }
    }
}

// ---------------- gemm body (device fn) ---------------------------------------
template <int K>
__device__ __forceinline__ void gemm_body(
    int blk, const float* __restrict__ Wl, const float* __restrict__ bl,
    const float* __restrict__ Wr, const float* __restrict__ br, int N,
    float* hs) {
    constexpr int MB = 32, LD = 34;
    const int n0 = blk * MB;
    const int j = threadIdx.x;

    for (int idx = threadIdx.x; idx < MB * K; idx += 256) {
        int m = idx / K, k = idx - m * K;
        int n = n0 + m;
        hs[k * LD + m] = (n < N) ? g_h[(size_t)n * K + k] : 0.f;
    }
    __syncthreads();

    ull accl[16], accr[16];
    float blj = bl[j], brj = br[j];
#pragma unroll
    for (int p = 0; p < 16; ++p) { accl[p] = pack2(blj, blj); accr[p] = pack2(brj, brj); }

#pragma unroll 4
    for (int k = 0; k < K; ++k) {
        float wl = Wl[k * 256 + j];
        float wr = Wr[k * 256 + j];
        ull wl2 = pack2(wl, wl), wr2 = pack2(wr, wr);
        const float* hrow = &hs[k * LD];
#pragma unroll
        for (int p = 0; p < 16; ++p) {
            ull hp = *reinterpret_cast<const ull*>(hrow + 2 * p);
            accl[p] = fma2(hp, wl2, accl[p]);
            accr[p] = fma2(hp, wr2, accr[p]);
        }
    }
#pragma unroll
    for (int p = 0; p < 16; ++p) {
        float l0, l1, r0, r1;
        unpack2(accl[p], l0, l1);
        unpack2(accr[p], r0, r1);
        int n = n0 + 2 * p;
        if (n < N)     { g_xl[(size_t)n * 256 + j] = l0; g_xr[(size_t)n * 256 + j] = r0; }
        if (n + 1 < N) { g_xl[(size_t)(n + 1) * 256 + j] = l1; g_xr[(size_t)(n + 1) * 256 + j] = r1; }
    }
}

// ---------------- launch 2: scatter + gemm1 (role-split blocks) --------------
__global__ __launch_bounds__(256) void scatter_gemm1(
    const int* __restrict__ src, const int* __restrict__ dst,
    const float* __restrict__ ea,
    const float* __restrict__ Wl, const float* __restrict__ bl,
    const float* __restrict__ Wr, const float* __restrict__ br,
    int N, int E, int ngemm) {
    __shared__ __align__(16) float hs[64 * 34];
    if ((int)blockIdx.x < ngemm) {
        gemm_body<64>(blockIdx.x, Wl, bl, Wr, br, N, hs);
    } else {
        int e = (blockIdx.x - ngemm) * 256 + threadIdx.x;
        if (e < E) {
            int d = dst[e];
            int pos = g_rowptr[d] + atomicAdd(&g_cur[d], 1);
            g_epair[pos] = make_int2(src[e], __float_as_int(ea[e]));
        }
    }
}

// ---------------- launch 4: gemm2 ---------------------------------------------
__global__ __launch_bounds__(256) void gemm2_kernel(
    const float* __restrict__ Wl, const float* __restrict__ bl,
    const float* __restrict__ Wr, const float* __restrict__ br, int N) {
    __shared__ __align__(16) float hs[256 * 34];
    gemm_body<256>(blockIdx.x, Wl, bl, Wr, br, N, hs);
}

// ---------------- launches 3 & 5: warp-per-dst online-softmax GAT --------------
// One warp owns one dst node; NO __syncthreads, NO smem. Edge pairs loaded
// lane-parallel and broadcast by shuffle; per-lane register accumulators.
template <bool LAST>
__global__ __launch_bounds__(256) void gat_fused(
    const float* __restrict__ We, const float* __restrict__ att,
    const float* __restrict__ bias, const int* __restrict__ batch, int N) {
    const int warp = threadIdx.x >> 5, lane = threadIdx.x & 31;
    const int d = blockIdx.x * 8 + warp;
    if (d >= N) return;

    const int start = g_rowptr[d];
    const int deg = g_rowptr[d + 1] - start;

    // per-lane slice of the 256-feature space: feats [4l,4l+4) and [128+4l,128+4l+4)
    const float4* xr4p  = reinterpret_cast<const float4*>(g_xr + (size_t)d * 256);
    const float4* We4p  = reinterpret_cast<const float4*>(We);
    const float4* att4p = reinterpret_cast<const float4*>(att);
    const float4* b4p   = reinterpret_cast<const float4*>(bias);

    if (deg > 0) {
        const float4 x0 = xr4p[lane],      e0 = We4p[lane],      t0 = att4p[lane];
        const float4 x1 = xr4p[lane + 32], e1 = We4p[lane + 32], t1 = att4p[lane + 32];

        float4 acc0 = {0.f, 0.f, 0.f, 0.f}, acc1 = {0.f, 0.f, 0.f, 0.f};
        const float NEG_INF = -__int_as_float(0x7f800000);
        float m0 = NEG_INF, m1 = NEG_INF, s0 = 0.f, s1 = 0.f;

        for (int base = 0; base < deg; base += 32) {
            int cnt = deg - base; if (cnt > 32) cnt = 32;
            int2 myep = (lane < cnt) ? g_epair[start + base + lane]
                                     : make_int2(0, 0);
            for (int i = 0; i < cnt; ++i) {
                int   s = __shfl_sync(0xffffffffu, myep.x, i);
                float w = __int_as_float(__shfl_sync(0xffffffffu, myep.y, i));
                const float4* xl4 = reinterpret_cast<const float4*>(g_xl + (size_t)s * 256);
                float4 a0 = xl4[lane];
                float4 a1 = xl4[lane + 32];

                float v, p0, p1;
                v = a0.x + x0.x + w * e0.x; v = (v > 0.f) ? v : 0.2f * v; p0 = v * t0.x;
                v = a0.y + x0.y + w * e0.y; v = (v > 0.f) ? v : 0.2f * v; p0 = fmaf(v, t0.y, p0);
                v = a0.z + x0.z + w * e0.z; v = (v > 0.f) ? v : 0.2f * v; p0 = fmaf(v, t0.z, p0);
                v = a0.w + x0.w + w * e0.w; v = (v > 0.f) ? v : 0.2f * v; p0 = fmaf(v, t0.w, p0);
                v = a1.x + x1.x + w * e1.x; v = (v > 0.f) ? v : 0.2f * v; p1 = v * t1.x;
                v = a1.y + x1.y + w * e1.y; v = (v > 0.f) ? v : 0.2f * v; p1 = fmaf(v, t1.y, p1);
                v = a1.z + x1.z + w * e1.z; v = (v > 0.f) ? v : 0.2f * v; p1 = fmaf(v, t1.z, p1);
                v = a1.w + x1.w + w * e1.w; v = (v > 0.f) ? v : 0.2f * v; p1 = fmaf(v, t1.w, p1);

                // half-warp reduce: every lane ends with ITS head's alpha
#pragma unroll
                for (int off = 8; off; off >>= 1) {
                    p0 += __shfl_xor_sync(0xffffffffu, p0, off);
                    p1 += __shfl_xor_sync(0xffffffffu, p1, off);
                }

                // online softmax update (per-lane, its own two heads)
                float nm0 = fmaxf(m0, p0);
                float sc0 = __expf(m0 - nm0);
                float ew0 = __expf(p0 - nm0);
                s0 = fmaf(s0, sc0, ew0); m0 = nm0;
                float nm1 = fmaxf(m1, p1);
                float sc1 = __expf(m1 - nm1);
                float ew1 = __expf(p1 - nm1);
                s1 = fmaf(s1, sc1, ew1); m1 = nm1;

                acc0.x = fmaf(acc0.x, sc0, ew0 * a0.x);
                acc0.y = fmaf(acc0.y, sc0, ew0 * a0.y);
                acc0.z = fmaf(acc0.z, sc0, ew0 * a0.z);
                acc0.w = fmaf(acc0.w, sc0, ew0 * a0.w);
                acc1.x = fmaf(acc1.x, sc1, ew1 * a1.x);
                acc1.y = fmaf(acc1.y, sc1, ew1 * a1.y);
                acc1.z = fmaf(acc1.z, sc1, ew1 * a1.z);
                acc1.w = fmaf(acc1.w, sc1, ew1 * a1.w);
            }
        }

        float inv0 = 1.f / (s0 + 1e-16f);
        float inv1 = 1.f / (s1 + 1e-16f);
        float4 bb0 = b4p[lane], bb1 = b4p[lane + 32];
        float4 o0, o1;
        o0.x = fmaxf(fmaf(acc0.x, inv0, bb0.x), 0.f);
        o0.y = fmaxf(fmaf(acc0.y, inv0, bb0.y), 0.f);
        o0.z = fmaxf(fmaf(acc0.z, inv0, bb0.z), 0.f);
        o0.w = fmaxf(fmaf(acc0.w, inv0, bb0.w), 0.f);
        o1.x = fmaxf(fmaf(acc1.x, inv1, bb1.x), 0.f);
        o1.y = fmaxf(fmaf(acc1.y, inv1, bb1.y), 0.f);
        o1.z = fmaxf(fmaf(acc1.z, inv1, bb1.z), 0.f);
        o1.w = fmaxf(fmaf(acc1.w, inv1, bb1.w), 0.f);

        if (LAST) {
            float* pool = g_pool + batch[d] * 256;
            atomicAdd(&pool[4 * lane + 0], o0.x);
            atomicAdd(&pool[4 * lane + 1], o0.y);
            atomicAdd(&pool[4 * lane + 2], o0.z);
            atomicAdd(&pool[4 * lane + 3], o0.w);
            atomicAdd(&pool[128 + 4 * lane + 0], o1.x);
            atomicAdd(&pool[128 + 4 * lane + 1], o1.y);
            atomicAdd(&pool[128 + 4 * lane + 2], o1.z);
            atomicAdd(&pool[128 + 4 * lane + 3], o1.w);
        } else {
            float4* hout = reinterpret_cast<float4*>(g_h + (size_t)d * 256);
            hout[lane] = o0;
            hout[lane + 32] = o1;
        }
    } else {
        float4 bb0 = b4p[lane], bb1 = b4p[lane + 32];
        float4 o0, o1;
        o0.x = fmaxf(bb0.x, 0.f); o0.y = fmaxf(bb0.y, 0.f);
        o0.z = fmaxf(bb0.z, 0.f); o0.w = fmaxf(bb0.w, 0.f);
        o1.x = fmaxf(bb1.x, 0.f); o1.y = fmaxf(bb1.y, 0.f);
        o1.z = fmaxf(bb1.z, 0.f); o1.w = fmaxf(bb1.w, 0.f);
        if (LAST) {
            float* pool = g_pool + batch[d] * 256;
            atomicAdd(&pool[4 * lane + 0], o0.x);
            atomicAdd(&pool[4 * lane + 1], o0.y);
            atomicAdd(&pool[4 * lane + 2], o0.z);
            atomicAdd(&pool[4 * lane + 3], o0.w);
            atomicAdd(&pool[128 + 4 * lane + 0], o1.x);
            atomicAdd(&pool[128 + 4 * lane + 1], o1.y);
            atomicAdd(&pool[128 + 4 * lane + 2], o1.z);
            atomicAdd(&pool[128 + 4 * lane + 3], o1.w);
        } else {
            float4* hout = reinterpret_cast<float4*>(g_h + (size_t)d * 256);
            hout[lane] = o0;
            hout[lane + 32] = o1;
        }
    }
}

// ---------------- launch 6: head MLP + scratch reset ---------------------------
__global__ __launch_bounds__(128) void mlp_kernel(
    const float* __restrict__ p1W, const float* __restrict__ p1b,
    const float* __restrict__ lng, const float* __restrict__ lnb,
    const float* __restrict__ p2W, const float* __restrict__ p2b,
    float* __restrict__ out, int G) {
    int g = blockIdx.x;
    __shared__ float ps[256];
    __shared__ float zs[128];
    __shared__ float red[128];
    float cnt = fmaxf(g_cnt[g], 1.f);
    for (int k = threadIdx.x; k < 256; k += 128)
        ps[k] = g_pool[g * 256 + k] / cnt;
    __syncthreads();
    if (threadIdx.x == 0) g_cnt[g] = 0.f;   // reset for next replay

    int j = threadIdx.x;
    float z = p1b[j];
    for (int k = 0; k < 256; ++k) z = fmaf(ps[k], p1W[k * 128 + j], z);

    red[j] = z;
    __syncthreads();
    for (int s = 64; s; s >>= 1) { if (j < s) red[j] += red[j + s]; __syncthreads(); }
    float mu = red[0] * (1.f / 128.f);
    __syncthreads();
    float dz = z - mu;
    red[j] = dz * dz;
    __syncthreads();
    for (int s = 64; s; s >>= 1) { if (j < s) red[j] += red[j + s]; __syncthreads(); }
    float var = red[0] * (1.f / 128.f);
    float zn = dz * rsqrtf(var + 1e-5f) * lng[j] + lnb[j];
    zs[j] = fmaxf(zn, 0.f);
    __syncthreads();

    if (j < 64) {
        float o = p2b[j];
        for (int k = 0; k < 128; ++k) o = fmaf(zs[k], p2W[k * 64 + j], o);
        out[g * 64 + j] = fmaxf(o, 0.f);
    }
}

// ---------------- driver ----------------------------------------------------------
extern "C" void kernel_launch(void* const* d_in, const int* in_sizes, int n_in,
                              void* d_out, int out_size) {
    const float* x      = (const float*)d_in[0];
    const int*   ei     = (const int*)  d_in[1];
    const float* ea     = (const float*)d_in[2];
    const int*   batch  = (const int*)  d_in[3];
    const float* enc_W  = (const float*)d_in[4];
    const float* enc_b  = (const float*)d_in[5];
    const float* g1_Wl  = (const float*)d_in[6];
    const float* g1_bl  = (const float*)d_in[7];
    const float* g1_Wr  = (const float*)d_in[8];
    const float* g1_br  = (const float*)d_in[9];
    const float* g1_We  = (const float*)d_in[10];
    const float* g1_att = (const float*)d_in[11];
    const float* g1_bias= (const float*)d_in[12];
    const float* g2_Wl  = (const float*)d_in[13];
    const float* g2_bl  = (const float*)d_in[14];
    const float* g2_Wr  = (const float*)d_in[15];
    const float* g2_br  = (const float*)d_in[16];
    const float* g2_We  = (const float*)d_in[17];
    const float* g2_att = (const float*)d_in[18];
    const float* g2_bias= (const float*)d_in[19];
    const float* p1_W   = (const float*)d_in[20];
    const float* p1_b   = (const float*)d_in[21];
    const float* ln_g   = (const float*)d_in[22];
    const float* ln_b   = (const float*)d_in[23];
    const float* p2_W   = (const float*)d_in[24];
    const float* p2_b   = (const float*)d_in[25];

    const int N = in_sizes[3];
    const int E = in_sizes[2];
    const int G = out_size / 64;
    const int* src = ei;
    const int* dst = ei + E;
    const int T = 256;

    // 0: encoder + degree hist + graph counts + pool zero
    enc_hist_kernel<<<(N * 64 + T - 1) / T, T>>>(x, enc_W, enc_b, dst, batch, N, E, G);
    // 1: rowptr scan (re-zeros g_deg)
    csr_scan<<<1, 1024>>>(N);
    // 2: edge scatter + layer-1 projections (role-split grid)
    {
        int ngemm = (N + 31) / 32;
        int nscat = (E + T - 1) / T;
        scatter_gemm1<<<ngemm + nscat, T>>>(src, dst, ea, g1_Wl, g1_bl,
                                            g1_Wr, g1_br, N, E, ngemm);
    }
    // 3: layer-1 fused GAT (warp-per-dst; profiled launch)
    gat_fused<false><<<(N + 7) / 8, 256>>>(g1_We, g1_att, g1_bias, batch, N);
    // 4: layer-2 projections
    gemm2_kernel<<<(N + 31) / 32, 256>>>(g2_Wl, g2_bl, g2_Wr, g2_br, N);
    // 5: layer-2 fused GAT -> pool
    gat_fused<true><<<(N + 7) / 8, 256>>>(g2_We, g2_att, g2_bias, batch, N);
    // 6: head MLP (+ g_cnt reset)
    mlp_kernel<<<G, 128>>>(p1_W, p1_b, ln_g, ln_b, p2_W, p2_b, (float*)d_out, G);
}